// round 15
// baseline (speedup 1.0000x reference)
#include <cuda_runtime.h>
#include <cuda_fp16.h>
#include <cstdint>

// Problem constants
constexpr int NB  = 8;
constexpr int SEQ = 2048;
constexpr int EMB = 1024;
constexpr int ROWS = NB * SEQ;                     // 16384
constexpr long long ROWE = (long long)ROWS * EMB;  // 16,777,216
constexpr int EE = EMB * EMB;                      // 1,048,576

// ---------------- scratch (device globals) ---------------------------------
__device__ __half g_ln[ROWE];                        // LN1 out -> LN2 out (fp16)
__device__ __half g_qkv[3 * ROWE];                   // Q | K | Vt (fp16)
__device__ float  g_big[(long long)ROWS * SEQ];      // scores (fp32)
__device__ __half g_att[(long long)ROWS * SEQ];      // softmax out (fp16)
__device__ __half g_h1[(long long)ROWS * 2 * EMB];   // MLP hidden (fp16)
__device__ float  g_x1[ROWE];                        // x + attn_out (fp32)
__device__ float  g_negbias[ROWS];                   // additive mask bias
__device__ __half g_wh[7 * EE];                      // fp16 weights: Wq|Wk|Wv|W1|W2
__device__ float  g_bias3[3 * EMB];                  // bq|bk|bv contiguous

__device__ __forceinline__ uint32_t h2u(__half2 h) {
    return *reinterpret_cast<uint32_t*>(&h);
}

// fast exp on FMA pipe (x <= 0 expected; clamped below -87)
__device__ __forceinline__ float fexp(float x) {
    x = fmaxf(x, -87.0f);
    float y = x * 1.44269504f;
    float z = y + 12582912.0f;          // 1.5*2^23 magic
    float kf = z - 12582912.0f;         // rint(y)
    float f = y - kf;                   // [-0.5, 0.5]
    float p = 0.00133336f;
    p = fmaf(p, f, 0.00961813f);
    p = fmaf(p, f, 0.05550411f);
    p = fmaf(p, f, 0.24022651f);
    p = fmaf(p, f, 0.69314718f);
    p = fmaf(p, f, 1.0f);
    int ik = (int)kf;
    return p * __int_as_float((ik + 127) << 23);
}

// ---------------- weight -> fp16 + bias pack --------------------------------
__global__ void round_all(const float4* __restrict__ Wq, const float4* __restrict__ Wk,
                          const float4* __restrict__ Wv, const float4* __restrict__ W1,
                          const float4* __restrict__ W2,
                          const float* __restrict__ bq, const float* __restrict__ bk,
                          const float* __restrict__ bv) {
    const int E4 = EE / 4;
    long long i = (long long)blockIdx.x * 256 + threadIdx.x;
    long long stride = (long long)gridDim.x * 256;
    uint2* dst = (uint2*)g_wh;
    for (long long j = i; j < 7LL * E4; j += stride) {
        float4 v;
        if (j < E4)              v = Wq[j];
        else if (j < 2LL * E4)   v = Wk[j - E4];
        else if (j < 3LL * E4)   v = Wv[j - 2LL * E4];
        else if (j < 5LL * E4)   v = W1[j - 3LL * E4];
        else                     v = W2[j - 5LL * E4];
        uint2 o;
        o.x = h2u(__floats2half2_rn(v.x, v.y));
        o.y = h2u(__floats2half2_rn(v.z, v.w));
        dst[j] = o;
    }
    if (i < EMB) {
        g_bias3[i] = bq[i];
        g_bias3[i + EMB] = bk[i];
        g_bias3[i + 2 * EMB] = bv[i];
    }
}

// ---------------- mask decode (dtype-robust) -------------------------------
__global__ void mask_kernel(const unsigned char* __restrict__ raw) {
    __shared__ int s_f32, s_u8;
    int t = threadIdx.x;
    if (t == 0) { s_f32 = 0; s_u8 = 0; }
    __syncthreads();
    int f32 = 0, u8 = 0;
    const unsigned int* dw = (const unsigned int*)raw;
    for (int i = t; i < 4096; i += 256) {
        unsigned int v = dw[i];
        if (v == 0x3F800000u) f32 = 1;
        else if (v & 0xFFFFFF00u) u8 = 1;
    }
    if (f32) atomicOr(&s_f32, 1);
    if (u8)  atomicOr(&s_u8, 1);
    __syncthreads();
    int mode = s_f32 ? 2 : (s_u8 ? 0 : 1);
    const int*   di = (const int*)raw;
    const float* df = (const float*)raw;
    for (int i = t; i < ROWS; i += 256) {
        bool m;
        if (mode == 0)      m = raw[i] != 0;
        else if (mode == 1) m = di[i] != 0;
        else                m = df[i] != 0.0f;
        g_negbias[i] = m ? -1e30f : 0.0f;
    }
}

// ---------------- layernorm (fp16 output) ----------------------------------
__global__ void ln_kernel(const float* __restrict__ x,
                          const float* __restrict__ w,
                          const float* __restrict__ bb,
                          __half* __restrict__ out) {
    long long row = blockIdx.x;
    const float4* xr = (const float4*)x + row * (EMB / 4);
    int t = threadIdx.x;
    float4 v = xr[t];
    float s  = v.x + v.y + v.z + v.w;
    float sq = v.x * v.x + v.y * v.y + v.z * v.z + v.w * v.w;
#pragma unroll
    for (int o = 16; o > 0; o >>= 1) {
        s  += __shfl_xor_sync(0xffffffffu, s,  o);
        sq += __shfl_xor_sync(0xffffffffu, sq, o);
    }
    __shared__ float ss[8], sqs[8];
    if ((t & 31) == 0) { ss[t >> 5] = s; sqs[t >> 5] = sq; }
    __syncthreads();
    float tot = 0.f, totq = 0.f;
#pragma unroll
    for (int i = 0; i < 8; i++) { tot += ss[i]; totq += sqs[i]; }
    float mu  = tot * (1.0f / EMB);
    float var = totq * (1.0f / EMB) - mu * mu;
    float inv = rsqrtf(var + 1e-5f);
    float4 wv = ((const float4*)w)[t];
    float4 bv = ((const float4*)bb)[t];
    uint2 o;
    o.x = h2u(__floats2half2_rn((v.x - mu) * inv * wv.x + bv.x,
                                (v.y - mu) * inv * wv.y + bv.y));
    o.y = h2u(__floats2half2_rn((v.z - mu) * inv * wv.z + bv.z,
                                (v.w - mu) * inv * wv.w + bv.w));
    ((uint2*)out)[row * (EMB / 4) + t] = o;
}

// ---------------- softmax rows of 2048: f32 in, fp16 out -------------------
__global__ void softmax_kernel(const float* __restrict__ sc,
                               __half* __restrict__ att) {
    long long row = blockIdx.x;
    const float4* p = (const float4*)sc + row * (SEQ / 4);
    int t = threadIdx.x;
    float4 a = p[t];
    float4 b = p[t + 256];
    float mx = fmaxf(fmaxf(fmaxf(a.x, a.y), fmaxf(a.z, a.w)),
                     fmaxf(fmaxf(b.x, b.y), fmaxf(b.z, b.w)));
#pragma unroll
    for (int o = 16; o > 0; o >>= 1) mx = fmaxf(mx, __shfl_xor_sync(0xffffffffu, mx, o));
    __shared__ float sm[8], ssum[8];
    if ((t & 31) == 0) sm[t >> 5] = mx;
    __syncthreads();
    float m8 = sm[0];
#pragma unroll
    for (int i = 1; i < 8; i++) m8 = fmaxf(m8, sm[i]);
    a.x = fexp(a.x - m8); a.y = fexp(a.y - m8);
    a.z = fexp(a.z - m8); a.w = fexp(a.w - m8);
    b.x = fexp(b.x - m8); b.y = fexp(b.y - m8);
    b.z = fexp(b.z - m8); b.w = fexp(b.w - m8);
    float sum = a.x + a.y + a.z + a.w + b.x + b.y + b.z + b.w;
#pragma unroll
    for (int o = 16; o > 0; o >>= 1) sum += __shfl_xor_sync(0xffffffffu, sum, o);
    if ((t & 31) == 0) ssum[t >> 5] = sum;
    __syncthreads();
    float tot = 0.f;
#pragma unroll
    for (int i = 0; i < 8; i++) tot += ssum[i];
    float inv = 1.0f / tot;
    uint2* po = (uint2*)(att + row * SEQ);
    uint2 oa, ob;
    oa.x = h2u(__floats2half2_rn(a.x * inv, a.y * inv));
    oa.y = h2u(__floats2half2_rn(a.z * inv, a.w * inv));
    ob.x = h2u(__floats2half2_rn(b.x * inv, b.y * inv));
    ob.y = h2u(__floats2half2_rn(b.z * inv, b.w * inv));
    po[t] = oa;
    po[t + 256] = ob;
}

// ---------------- async-copy / ldmatrix helpers ----------------------------
__device__ __forceinline__ uint32_t smem_u32(const void* p) {
    uint32_t a;
    asm("{ .reg .u64 t; cvta.to.shared.u64 t, %1; cvt.u32.u64 %0, t; }"
        : "=r"(a) : "l"(p));
    return a;
}
__device__ __forceinline__ void cpa(uint32_t dst, const void* src) {
    asm volatile("cp.async.cg.shared.global [%0], [%1], 16;"
                 :: "r"(dst), "l"(src) : "memory");
}
__device__ __forceinline__ void cpa_commit() {
    asm volatile("cp.async.commit_group;" ::: "memory");
}
template <int N> __device__ __forceinline__ void cpa_wait() {
    asm volatile("cp.async.wait_group %0;" :: "n"(N) : "memory");
}
__device__ __forceinline__ void ldsm4(uint32_t* r, uint32_t addr) {
    asm volatile("ldmatrix.sync.aligned.m8n8.x4.shared.b16 {%0,%1,%2,%3}, [%4];"
                 : "=r"(r[0]), "=r"(r[1]), "=r"(r[2]), "=r"(r[3]) : "r"(addr));
}
__device__ __forceinline__ void mma16(float* d, const uint32_t* a,
                                      uint32_t b0, uint32_t b1) {
    asm volatile(
        "mma.sync.aligned.m16n8k16.row.col.f32.f16.f16.f32 "
        "{%0,%1,%2,%3}, {%4,%5,%6,%7}, {%8,%9}, {%0,%1,%2,%3};"
        : "+f"(d[0]), "+f"(d[1]), "+f"(d[2]), "+f"(d[3])
        : "r"(a[0]), "r"(a[1]), "r"(a[2]), "r"(a[3]), "r"(b0), "r"(b1));
}

// ---------------- fp16 mma.sync GEMM: CTA 128x128, BK=64, 3-stage ----------
// C[i,j] = sum_k A[i,k]*B[j,k]  (A,B fp16 K-major; accum fp32)
// EPI: 2 *scale+biascol -> f32 | 3 +res -> f32 | 4 relu(+bias) -> fp16
//      5 +bias+res -> f32 | 7 +bias[z] -> fp16, z==2 transposed (QKV)
constexpr int LDTH = 72;                        // halves per padded row (144B)
constexpr int STAGEH = 256 * LDTH;              // halves per stage (A128+B128)
constexpr int DSMEM_BYTES = 3 * STAGEH * 2;     // 110592

template <int EPI>
__global__ void __launch_bounds__(128)
mma_gemm(const __half* __restrict__ Abase, const __half* __restrict__ Bbase,
         void* __restrict__ Cvbase, int K, int lda, int ldb, int ldc,
         const float* __restrict__ biasBase, const float* __restrict__ resBase,
         float scale, long long strA, long long strB, long long strC,
         long long strBias, long long strRes) {
    extern __shared__ __half hsm[];
    const int z = blockIdx.z;
    const __half* A = Abase + (long long)z * strA;
    const __half* B = Bbase + (long long)z * strB;
    const float* bias = biasBase + (long long)z * strBias;
    const float* res  = resBase  + (long long)z * strRes;

    const int tid  = threadIdx.x;
    const int row0 = blockIdx.y * 128;
    const int col0 = blockIdx.x * 128;
    const uint32_t sb = smem_u32(hsm);

    const int wid = tid >> 5, lane = tid & 31;
    const int wm = wid & 1, wn = wid >> 1;      // warp 64x64 tile
    const int g = lane >> 2, c4 = lane & 3;

    // ldmatrix lane-address offsets (bytes, relative to stage base)
    const int aRow = wm * 64 + (lane & 15);
    const uint32_t aOff = (uint32_t)(aRow * LDTH + (lane >> 4) * 8) * 2u;
    const int bRowSel = (lane < 8) ? lane : ((lane < 24) ? lane - 8 : lane - 16);
    const uint32_t bOff = 128u * LDTH * 2u
                        + (uint32_t)((wn * 64 + bRowSel) * LDTH + ((lane >> 3) & 1) * 8) * 2u;

    float acc[4][8][4];
#pragma unroll
    for (int mt = 0; mt < 4; ++mt)
#pragma unroll
        for (int nt = 0; nt < 8; ++nt)
#pragma unroll
            for (int r = 0; r < 4; ++r) acc[mt][nt][r] = 0.f;

    auto load_chunk = [&](int c, int st) {
        const int k0 = c << 6;
        const uint32_t aB = sb + (uint32_t)st * (STAGEH * 2);
        // A: 128 rows x 64 halves (8 x 16B per thread)
#pragma unroll
        for (int j = 0; j < 8; ++j) {
            int idx = tid + 128 * j;
            int r = idx >> 3, q = idx & 7;
            cpa(aB + (uint32_t)(r * LDTH + q * 8) * 2,
                A + (long long)(row0 + r) * lda + k0 + q * 8);
        }
        const uint32_t bB = aB + 128u * LDTH * 2u;
#pragma unroll
        for (int j = 0; j < 8; ++j) {
            int idx = tid + 128 * j;
            int r = idx >> 3, q = idx & 7;
            cpa(bB + (uint32_t)(r * LDTH + q * 8) * 2,
                B + (long long)(col0 + r) * ldb + k0 + q * 8);
        }
    };

    const int NC = K >> 6;
    load_chunk(0, 0); cpa_commit();
    load_chunk(1, 1); cpa_commit();

    int stage = 0;       // stage of chunk c
    int wstage = 2;      // stage to fill with chunk c+2
    for (int c = 0; c < NC; ++c) {
        cpa_wait<1>();
        __syncthreads();
        if (c + 2 < NC) load_chunk(c + 2, wstage);
        cpa_commit();

        const uint32_t stBase = sb + (uint32_t)stage * (STAGEH * 2);
        const uint32_t aAddr = stBase + aOff;
        const uint32_t bAddr = stBase + bOff;

        uint32_t af[2][4][4];
        uint32_t bf[2][4][4];
        // preload kk=0 fragments (k0..15)
#pragma unroll
        for (int mt = 0; mt < 4; ++mt)
            ldsm4(af[0][mt], aAddr + (uint32_t)(mt * 16 * LDTH) * 2u);
#pragma unroll
        for (int np = 0; np < 4; ++np)
            ldsm4(bf[0][np], bAddr + (uint32_t)(np * 16 * LDTH) * 2u);

#pragma unroll
        for (int kk = 0; kk < 4; ++kk) {
            const int cur = kk & 1, nxt = cur ^ 1;
            if (kk < 3) {
                const uint32_t ko = (uint32_t)((kk + 1) * 16) * 2u;  // +16 halves
#pragma unroll
                for (int mt = 0; mt < 4; ++mt)
                    ldsm4(af[nxt][mt], aAddr + (uint32_t)(mt * 16 * LDTH) * 2u + ko);
#pragma unroll
                for (int np = 0; np < 4; ++np)
                    ldsm4(bf[nxt][np], bAddr + (uint32_t)(np * 16 * LDTH) * 2u + ko);
            }
#pragma unroll
            for (int np = 0; np < 4; ++np)
#pragma unroll
                for (int mt = 0; mt < 4; ++mt) {
                    mma16(acc[mt][2 * np],     af[cur][mt], bf[cur][np][0], bf[cur][np][1]);
                    mma16(acc[mt][2 * np + 1], af[cur][mt], bf[cur][np][2], bf[cur][np][3]);
                }
        }

        stage  = (stage == 2)  ? 0 : stage + 1;
        wstage = (wstage == 2) ? 0 : wstage + 1;
    }

    // ---- epilogue ----
#pragma unroll
    for (int mt = 0; mt < 4; ++mt) {
#pragma unroll
        for (int rr = 0; rr < 2; ++rr) {
            const long long m = row0 + wm * 64 + mt * 16 + g + rr * 8;
#pragma unroll
            for (int nt = 0; nt < 8; ++nt) {
                const int jc = col0 + wn * 64 + nt * 8 + c4 * 2;
                float v0 = acc[mt][nt][rr * 2 + 0];
                float v1 = acc[mt][nt][rr * 2 + 1];
                if (EPI == 2) {
                    float2 bb = *(const float2*)(bias + jc);
                    v0 = v0 * scale + bb.x;
                    v1 = v1 * scale + bb.y;
                } else if (EPI == 4 || EPI == 5 || EPI == 7) {
                    float2 bb = *(const float2*)(bias + jc);
                    v0 += bb.x; v1 += bb.y;
                }
                if (EPI == 4) { v0 = fmaxf(v0, 0.f); v1 = fmaxf(v1, 0.f); }
                if (EPI == 3 || EPI == 5) {
                    float2 rv = *(const float2*)(res + m * ldc + jc);
                    v0 += rv.x; v1 += rv.y;
                }
                if (EPI == 2 || EPI == 3 || EPI == 5) {
                    float* C = (float*)Cvbase + (long long)z * strC;
                    *(float2*)(C + m * ldc + jc) = make_float2(v0, v1);
                } else if (EPI == 7) {
                    __half* C = (__half*)Cvbase + (long long)z * strC;
                    if (z == 2) {
                        const int bb2 = (int)(m >> 11);
                        const int srow = (int)(m & 2047);
                        __half* cp = C + (long long)bb2 * ((long long)EMB * SEQ) + srow;
                        cp[(long long)jc * SEQ] = __float2half_rn(v0);
                        cp[(long long)(jc + 1) * SEQ] = __float2half_rn(v1);
                    } else {
                        __half2 hv = __floats2half2_rn(v0, v1);
                        *(__half2*)(C + m * ldc + jc) = hv;
                    }
                } else {  // EPI == 4
                    __half* C = (__half*)Cvbase + (long long)z * strC;
                    __half2 hv = __floats2half2_rn(v0, v1);
                    *(__half2*)(C + m * ldc + jc) = hv;
                }
            }
        }
    }
}

// ---------------- launch ----------------------------------------------------
extern "C" void kernel_launch(void* const* d_in, const int* in_sizes, int n_in,
                              void* d_out, int out_size) {
    (void)in_sizes; (void)n_in; (void)out_size;
    const float* x     = (const float*)d_in[0];
    const unsigned char* mask = (const unsigned char*)d_in[1];
    const float* ln1_w = (const float*)d_in[2];
    const float* ln1_b = (const float*)d_in[3];
    const float* ln2_w = (const float*)d_in[4];
    const float* ln2_b = (const float*)d_in[5];
    const float* Wq = (const float*)d_in[6];
    const float* bq = (const float*)d_in[7];
    const float* Wk = (const float*)d_in[8];
    const float* bk = (const float*)d_in[9];
    const float* Wv = (const float*)d_in[10];
    const float* bv = (const float*)d_in[11];
    const float* W1 = (const float*)d_in[12];
    const float* b1 = (const float*)d_in[13];
    const float* W2 = (const float*)d_in[14];
    const float* b2 = (const float*)d_in[15];
    float* out = (float*)d_out;

    __half *lnh, *qkvh, *atth, *h1h, *wh;
    float *big, *x1, *nb, *b3;
    cudaGetSymbolAddress((void**)&lnh,  g_ln);
    cudaGetSymbolAddress((void**)&qkvh, g_qkv);
    cudaGetSymbolAddress((void**)&big,  g_big);
    cudaGetSymbolAddress((void**)&atth, g_att);
    cudaGetSymbolAddress((void**)&h1h,  g_h1);
    cudaGetSymbolAddress((void**)&x1,   g_x1);
    cudaGetSymbolAddress((void**)&nb,   g_negbias);
    cudaGetSymbolAddress((void**)&wh,   g_wh);
    cudaGetSymbolAddress((void**)&b3,   g_bias3);

    cudaFuncSetAttribute(mma_gemm<2>, cudaFuncAttributeMaxDynamicSharedMemorySize, DSMEM_BYTES);
    cudaFuncSetAttribute(mma_gemm<3>, cudaFuncAttributeMaxDynamicSharedMemorySize, DSMEM_BYTES);
    cudaFuncSetAttribute(mma_gemm<4>, cudaFuncAttributeMaxDynamicSharedMemorySize, DSMEM_BYTES);
    cudaFuncSetAttribute(mma_gemm<5>, cudaFuncAttributeMaxDynamicSharedMemorySize, DSMEM_BYTES);
    cudaFuncSetAttribute(mma_gemm<7>, cudaFuncAttributeMaxDynamicSharedMemorySize, DSMEM_BYTES);

    __half* Qh = qkvh;
    __half* Kh = qkvh + ROWE;
    __half* Vth = qkvh + 2 * ROWE;
    __half* W1h = wh + 3 * EE;
    __half* W2h = wh + 5 * EE;

    const long long SE = (long long)SEQ * EMB;
    const long long SS = (long long)SEQ * SEQ;

    // 1) weights -> fp16 + pack biases
    round_all<<<4096, 256>>>((const float4*)Wq, (const float4*)Wk, (const float4*)Wv,
                             (const float4*)W1, (const float4*)W2, bq, bk, bv);
    // 2) mask -> additive bias
    mask_kernel<<<1, 256>>>(mask);
    // 3) LN1 -> fp16
    ln_kernel<<<ROWS, 256>>>(x, ln1_w, ln1_b, lnh);
    // 4) Q,K,V batched over z (z==2 stores V transposed into Vt)
    mma_gemm<7><<<dim3(EMB / 128, ROWS / 128, 3), 128, DSMEM_BYTES>>>(
        lnh, wh, (void*)qkvh, EMB, EMB, EMB, EMB, b3, x, 1.f,
        0, EE, ROWE, EMB, 0);
    // 5) scores = Q K^T / 32 + maskbias  (f32 out)
    mma_gemm<2><<<dim3(SEQ / 128, SEQ / 128, NB), 128, DSMEM_BYTES>>>(
        Qh, Kh, (void*)big, EMB, EMB, EMB, SEQ, nb, x, 0.03125f, SE, SE, SS, SEQ, 0);
    // 6) softmax rows -> fp16
    softmax_kernel<<<ROWS, 256>>>(big, atth);
    // 7) x1 = x + attn @ V
    mma_gemm<3><<<dim3(EMB / 128, SEQ / 128, NB), 128, DSMEM_BYTES>>>(
        atth, Vth, (void*)x1, SEQ, SEQ, SEQ, EMB, nb, x, 1.f, SS, SE, SE, 0, SE);
    // 8) LN2 -> fp16
    ln_kernel<<<ROWS, 256>>>(x1, ln2_w, ln2_b, lnh);
    // 9) h1 = relu(h @ W1^T + b1) -> fp16
    mma_gemm<4><<<dim3(2 * EMB / 128, ROWS / 128, 1), 128, DSMEM_BYTES>>>(
        lnh, W1h, (void*)h1h, EMB, EMB, EMB, 2 * EMB, b1, x, 1.f, 0, 0, 0, 0, 0);
    // 10) out = x1 + h1 @ W2^T + b2  (f32 out)
    mma_gemm<5><<<dim3(EMB / 128, ROWS / 128, 1), 128, DSMEM_BYTES>>>(
        h1h, W2h, (void*)out, 2 * EMB, 2 * EMB, 2 * EMB, EMB, b2, x1, 1.f, 0, 0, 0, 0, 0);
}

// round 16
// speedup vs baseline: 1.0186x; 1.0186x over previous
#include <cuda_runtime.h>
#include <cuda_fp16.h>
#include <cstdint>

// Problem constants
constexpr int NB  = 8;
constexpr int SEQ = 2048;
constexpr int EMB = 1024;
constexpr int ROWS = NB * SEQ;                     // 16384
constexpr long long ROWE = (long long)ROWS * EMB;  // 16,777,216
constexpr int EE = EMB * EMB;                      // 1,048,576

// ---------------- scratch (device globals) ---------------------------------
__device__ __half g_ln[ROWE];                        // LN1 out -> LN2 out (fp16)
__device__ __half g_qkv[3 * ROWE];                   // Q | K | Vt (fp16)
__device__ __half g_att[(long long)ROWS * SEQ];      // scores -> softmax (fp16, in place)
__device__ __half g_h1[(long long)ROWS * 2 * EMB];   // MLP hidden (fp16)
__device__ float  g_x1[ROWE];                        // x + attn_out (fp32)
__device__ float  g_negbias[ROWS];                   // additive mask bias
__device__ __half g_wh[7 * EE];                      // fp16 weights: Wq|Wk|Wv|W1|W2
__device__ float  g_bias3[3 * EMB];                  // bq|bk|bv contiguous

__device__ __forceinline__ uint32_t h2u(__half2 h) {
    return *reinterpret_cast<uint32_t*>(&h);
}
__device__ __forceinline__ __half2 u2h(uint32_t u) {
    return *reinterpret_cast<__half2*>(&u);
}

// fast exp on FMA pipe (x <= 0 expected; clamped below -87)
__device__ __forceinline__ float fexp(float x) {
    x = fmaxf(x, -87.0f);
    float y = x * 1.44269504f;
    float z = y + 12582912.0f;          // 1.5*2^23 magic
    float kf = z - 12582912.0f;         // rint(y)
    float f = y - kf;                   // [-0.5, 0.5]
    float p = 0.00133336f;
    p = fmaf(p, f, 0.00961813f);
    p = fmaf(p, f, 0.05550411f);
    p = fmaf(p, f, 0.24022651f);
    p = fmaf(p, f, 0.69314718f);
    p = fmaf(p, f, 1.0f);
    int ik = (int)kf;
    return p * __int_as_float((ik + 127) << 23);
}

// ---------------- weight -> fp16 + bias pack --------------------------------
__global__ void round_all(const float4* __restrict__ Wq, const float4* __restrict__ Wk,
                          const float4* __restrict__ Wv, const float4* __restrict__ W1,
                          const float4* __restrict__ W2,
                          const float* __restrict__ bq, const float* __restrict__ bk,
                          const float* __restrict__ bv) {
    const int E4 = EE / 4;
    long long i = (long long)blockIdx.x * 256 + threadIdx.x;
    long long stride = (long long)gridDim.x * 256;
    uint2* dst = (uint2*)g_wh;
    for (long long j = i; j < 7LL * E4; j += stride) {
        float4 v;
        if (j < E4)              v = Wq[j];
        else if (j < 2LL * E4)   v = Wk[j - E4];
        else if (j < 3LL * E4)   v = Wv[j - 2LL * E4];
        else if (j < 5LL * E4)   v = W1[j - 3LL * E4];
        else                     v = W2[j - 5LL * E4];
        uint2 o;
        o.x = h2u(__floats2half2_rn(v.x, v.y));
        o.y = h2u(__floats2half2_rn(v.z, v.w));
        dst[j] = o;
    }
    if (i < EMB) {
        g_bias3[i] = bq[i];
        g_bias3[i + EMB] = bk[i];
        g_bias3[i + 2 * EMB] = bv[i];
    }
}

// ---------------- mask decode (dtype-robust) -------------------------------
__global__ void mask_kernel(const unsigned char* __restrict__ raw) {
    __shared__ int s_f32, s_u8;
    int t = threadIdx.x;
    if (t == 0) { s_f32 = 0; s_u8 = 0; }
    __syncthreads();
    int f32 = 0, u8 = 0;
    const unsigned int* dw = (const unsigned int*)raw;
    for (int i = t; i < 4096; i += 256) {
        unsigned int v = dw[i];
        if (v == 0x3F800000u) f32 = 1;
        else if (v & 0xFFFFFF00u) u8 = 1;
    }
    if (f32) atomicOr(&s_f32, 1);
    if (u8)  atomicOr(&s_u8, 1);
    __syncthreads();
    int mode = s_f32 ? 2 : (s_u8 ? 0 : 1);
    const int*   di = (const int*)raw;
    const float* df = (const float*)raw;
    for (int i = t; i < ROWS; i += 256) {
        bool m;
        if (mode == 0)      m = raw[i] != 0;
        else if (mode == 1) m = di[i] != 0;
        else                m = df[i] != 0.0f;
        g_negbias[i] = m ? -1e30f : 0.0f;
    }
}

// ---------------- layernorm (fp16 output) ----------------------------------
__global__ void ln_kernel(const float* __restrict__ x,
                          const float* __restrict__ w,
                          const float* __restrict__ bb,
                          __half* __restrict__ out) {
    long long row = blockIdx.x;
    const float4* xr = (const float4*)x + row * (EMB / 4);
    int t = threadIdx.x;
    float4 v = xr[t];
    float s  = v.x + v.y + v.z + v.w;
    float sq = v.x * v.x + v.y * v.y + v.z * v.z + v.w * v.w;
#pragma unroll
    for (int o = 16; o > 0; o >>= 1) {
        s  += __shfl_xor_sync(0xffffffffu, s,  o);
        sq += __shfl_xor_sync(0xffffffffu, sq, o);
    }
    __shared__ float ss[8], sqs[8];
    if ((t & 31) == 0) { ss[t >> 5] = s; sqs[t >> 5] = sq; }
    __syncthreads();
    float tot = 0.f, totq = 0.f;
#pragma unroll
    for (int i = 0; i < 8; i++) { tot += ss[i]; totq += sqs[i]; }
    float mu  = tot * (1.0f / EMB);
    float var = totq * (1.0f / EMB) - mu * mu;
    float inv = rsqrtf(var + 1e-5f);
    float4 wv = ((const float4*)w)[t];
    float4 bv = ((const float4*)bb)[t];
    uint2 o;
    o.x = h2u(__floats2half2_rn((v.x - mu) * inv * wv.x + bv.x,
                                (v.y - mu) * inv * wv.y + bv.y));
    o.y = h2u(__floats2half2_rn((v.z - mu) * inv * wv.z + bv.z,
                                (v.w - mu) * inv * wv.w + bv.w));
    ((uint2*)out)[row * (EMB / 4) + t] = o;
}

// ---------------- softmax rows of 2048: fp16 in/out, in place --------------
__global__ void softmax_kernel(__half* __restrict__ sc) {
    long long row = blockIdx.x;
    uint4* p = (uint4*)(sc + row * SEQ);
    int t = threadIdx.x;
    uint4 u = p[t];
    float f[8];
    {
        __half2 h0 = u2h(u.x), h1 = u2h(u.y), h2 = u2h(u.z), h3 = u2h(u.w);
        float2 a0 = __half22float2(h0), a1 = __half22float2(h1);
        float2 a2 = __half22float2(h2), a3 = __half22float2(h3);
        f[0] = a0.x; f[1] = a0.y; f[2] = a1.x; f[3] = a1.y;
        f[4] = a2.x; f[5] = a2.y; f[6] = a3.x; f[7] = a3.y;
    }
    float mx = f[0];
#pragma unroll
    for (int i = 1; i < 8; i++) mx = fmaxf(mx, f[i]);
#pragma unroll
    for (int o = 16; o > 0; o >>= 1) mx = fmaxf(mx, __shfl_xor_sync(0xffffffffu, mx, o));
    __shared__ float sm[8], ssum[8];
    if ((t & 31) == 0) sm[t >> 5] = mx;
    __syncthreads();
    float m8 = sm[0];
#pragma unroll
    for (int i = 1; i < 8; i++) m8 = fmaxf(m8, sm[i]);
    float sum = 0.f;
#pragma unroll
    for (int i = 0; i < 8; i++) { f[i] = fexp(f[i] - m8); sum += f[i]; }
#pragma unroll
    for (int o = 16; o > 0; o >>= 1) sum += __shfl_xor_sync(0xffffffffu, sum, o);
    if ((t & 31) == 0) ssum[t >> 5] = sum;
    __syncthreads();
    float tot = 0.f;
#pragma unroll
    for (int i = 0; i < 8; i++) tot += ssum[i];
    float inv = 1.0f / tot;
    uint4 o;
    o.x = h2u(__floats2half2_rn(f[0] * inv, f[1] * inv));
    o.y = h2u(__floats2half2_rn(f[2] * inv, f[3] * inv));
    o.z = h2u(__floats2half2_rn(f[4] * inv, f[5] * inv));
    o.w = h2u(__floats2half2_rn(f[6] * inv, f[7] * inv));
    p[t] = o;
}

// ---------------- async-copy / ldmatrix helpers ----------------------------
__device__ __forceinline__ uint32_t smem_u32(const void* p) {
    uint32_t a;
    asm("{ .reg .u64 t; cvta.to.shared.u64 t, %1; cvt.u32.u64 %0, t; }"
        : "=r"(a) : "l"(p));
    return a;
}
__device__ __forceinline__ void cpa(uint32_t dst, const void* src) {
    asm volatile("cp.async.cg.shared.global [%0], [%1], 16;"
                 :: "r"(dst), "l"(src) : "memory");
}
__device__ __forceinline__ void cpa_commit() {
    asm volatile("cp.async.commit_group;" ::: "memory");
}
template <int N> __device__ __forceinline__ void cpa_wait() {
    asm volatile("cp.async.wait_group %0;" :: "n"(N) : "memory");
}
__device__ __forceinline__ void ldsm4(uint32_t* r, uint32_t addr) {
    asm volatile("ldmatrix.sync.aligned.m8n8.x4.shared.b16 {%0,%1,%2,%3}, [%4];"
                 : "=r"(r[0]), "=r"(r[1]), "=r"(r[2]), "=r"(r[3]) : "r"(addr));
}
__device__ __forceinline__ void mma16(float* d, const uint32_t* a,
                                      uint32_t b0, uint32_t b1) {
    asm volatile(
        "mma.sync.aligned.m16n8k16.row.col.f32.f16.f16.f32 "
        "{%0,%1,%2,%3}, {%4,%5,%6,%7}, {%8,%9}, {%0,%1,%2,%3};"
        : "+f"(d[0]), "+f"(d[1]), "+f"(d[2]), "+f"(d[3])
        : "r"(a[0]), "r"(a[1]), "r"(a[2]), "r"(a[3]), "r"(b0), "r"(b1));
}

// ---------------- fp16 mma.sync GEMM: CTA 128x128, BK=32, 4-stage ----------
// C[i,j] = sum_k A[i,k]*B[j,k]  (A,B fp16 K-major; accum fp32)
// EPI: 2 *scale+biascol -> fp16 (scores) | 3 +res -> f32 | 4 relu(+bias) -> fp16
//      5 +bias+res -> f32 | 7 +bias[z] -> fp16, z==2 transposed (QKV)
constexpr int LDTH = 40;                        // halves per padded row (80B)
constexpr int STAGEH = 256 * LDTH;              // halves per stage (A128+B128)
constexpr int DSMEM_BYTES = 4 * STAGEH * 2;     // 81920

template <int EPI>
__global__ void __launch_bounds__(128)
mma_gemm(const __half* __restrict__ Abase, const __half* __restrict__ Bbase,
         void* __restrict__ Cvbase, int K, int lda, int ldb, int ldc,
         const float* __restrict__ biasBase, const float* __restrict__ resBase,
         float scale, long long strA, long long strB, long long strC,
         long long strBias, long long strRes) {
    extern __shared__ __half hsm[];
    const int z = blockIdx.z;
    const __half* A = Abase + (long long)z * strA;
    const __half* B = Bbase + (long long)z * strB;
    const float* bias = biasBase + (long long)z * strBias;
    const float* res  = resBase  + (long long)z * strRes;

    const int tid  = threadIdx.x;
    const int row0 = blockIdx.y * 128;
    const int col0 = blockIdx.x * 128;
    const uint32_t sb = smem_u32(hsm);

    const int wid = tid >> 5, lane = tid & 31;
    const int wm = wid & 1, wn = wid >> 1;      // warp 64x64 tile
    const int g = lane >> 2, c4 = lane & 3;

    // ldmatrix lane-address offsets (bytes, relative to stage base)
    const int aRow = wm * 64 + (lane & 15);
    const uint32_t aOff = (uint32_t)(aRow * LDTH + (lane >> 4) * 8) * 2u;
    const int bRowSel = (lane < 8) ? lane : ((lane < 24) ? lane - 8 : lane - 16);
    const uint32_t bOff = 128u * LDTH * 2u
                        + (uint32_t)((wn * 64 + bRowSel) * LDTH + ((lane >> 3) & 1) * 8) * 2u;

    float acc[4][8][4];
#pragma unroll
    for (int mt = 0; mt < 4; ++mt)
#pragma unroll
        for (int nt = 0; nt < 8; ++nt)
#pragma unroll
            for (int r = 0; r < 4; ++r) acc[mt][nt][r] = 0.f;

    auto load_chunk = [&](int c, int st) {
        const int k0 = c << 5;
        const uint32_t aB = sb + (uint32_t)st * (STAGEH * 2);
#pragma unroll
        for (int j = 0; j < 4; ++j) {
            int idx = tid + 128 * j;
            int r = idx >> 2, q = idx & 3;
            cpa(aB + (uint32_t)(r * LDTH + q * 8) * 2,
                A + (long long)(row0 + r) * lda + k0 + q * 8);
        }
        const uint32_t bB = aB + 128u * LDTH * 2u;
#pragma unroll
        for (int j = 0; j < 4; ++j) {
            int idx = tid + 128 * j;
            int r = idx >> 2, q = idx & 3;
            cpa(bB + (uint32_t)(r * LDTH + q * 8) * 2,
                B + (long long)(col0 + r) * ldb + k0 + q * 8);
        }
    };

    const int NC = K >> 5;
    load_chunk(0, 0); cpa_commit();
    load_chunk(1, 1); cpa_commit();
    load_chunk(2, 2); cpa_commit();

    int stage = 0;       // stage of chunk c
    int wstage = 3;      // stage to fill with chunk c+3
    for (int c = 0; c < NC; ++c) {
        cpa_wait<2>();
        __syncthreads();
        if (c + 3 < NC) load_chunk(c + 3, wstage);
        cpa_commit();

        const uint32_t stBase = sb + (uint32_t)stage * (STAGEH * 2);
        const uint32_t aAddr = stBase + aOff;
        const uint32_t bAddr = stBase + bOff;

        uint32_t af[2][4][4];
        uint32_t bf[2][4][4];
        // preload kk=0 fragments (k0..15)
#pragma unroll
        for (int mt = 0; mt < 4; ++mt)
            ldsm4(af[0][mt], aAddr + (uint32_t)(mt * 16 * LDTH) * 2u);
#pragma unroll
        for (int np = 0; np < 4; ++np)
            ldsm4(bf[0][np], bAddr + (uint32_t)(np * 16 * LDTH) * 2u);
        // prefetch kk=1 (k16..31, +32 bytes)
#pragma unroll
        for (int mt = 0; mt < 4; ++mt)
            ldsm4(af[1][mt], aAddr + (uint32_t)(mt * 16 * LDTH) * 2u + 32u);
#pragma unroll
        for (int np = 0; np < 4; ++np)
            ldsm4(bf[1][np], bAddr + (uint32_t)(np * 16 * LDTH) * 2u + 32u);

#pragma unroll
        for (int kk = 0; kk < 2; ++kk) {
#pragma unroll
            for (int np = 0; np < 4; ++np)
#pragma unroll
                for (int mt = 0; mt < 4; ++mt) {
                    mma16(acc[mt][2 * np],     af[kk][mt], bf[kk][np][0], bf[kk][np][1]);
                    mma16(acc[mt][2 * np + 1], af[kk][mt], bf[kk][np][2], bf[kk][np][3]);
                }
        }

        stage  = (stage == 3)  ? 0 : stage + 1;
        wstage = (wstage == 3) ? 0 : wstage + 1;
    }

    // ---- epilogue ----
#pragma unroll
    for (int mt = 0; mt < 4; ++mt) {
#pragma unroll
        for (int rr = 0; rr < 2; ++rr) {
            const long long m = row0 + wm * 64 + mt * 16 + g + rr * 8;
#pragma unroll
            for (int nt = 0; nt < 8; ++nt) {
                const int jc = col0 + wn * 64 + nt * 8 + c4 * 2;
                float v0 = acc[mt][nt][rr * 2 + 0];
                float v1 = acc[mt][nt][rr * 2 + 1];
                if (EPI == 2) {
                    float2 bb = *(const float2*)(bias + jc);
                    v0 = v0 * scale + bb.x;
                    v1 = v1 * scale + bb.y;
                } else if (EPI == 4 || EPI == 5 || EPI == 7) {
                    float2 bb = *(const float2*)(bias + jc);
                    v0 += bb.x; v1 += bb.y;
                }
                if (EPI == 4) { v0 = fmaxf(v0, 0.f); v1 = fmaxf(v1, 0.f); }
                if (EPI == 3 || EPI == 5) {
                    float2 rv = *(const float2*)(res + m * ldc + jc);
                    v0 += rv.x; v1 += rv.y;
                }
                if (EPI == 3 || EPI == 5) {
                    float* C = (float*)Cvbase + (long long)z * strC;
                    *(float2*)(C + m * ldc + jc) = make_float2(v0, v1);
                } else if (EPI == 7) {
                    __half* C = (__half*)Cvbase + (long long)z * strC;
                    if (z == 2) {
                        const int bb2 = (int)(m >> 11);
                        const int srow = (int)(m & 2047);
                        __half* cp = C + (long long)bb2 * ((long long)EMB * SEQ) + srow;
                        cp[(long long)jc * SEQ] = __float2half_rn(v0);
                        cp[(long long)(jc + 1) * SEQ] = __float2half_rn(v1);
                    } else {
                        __half2 hv = __floats2half2_rn(v0, v1);
                        *(__half2*)(C + m * ldc + jc) = hv;
                    }
                } else {  // EPI == 2 or 4 -> fp16 store
                    __half* C = (__half*)Cvbase + (long long)z * strC;
                    __half2 hv = __floats2half2_rn(v0, v1);
                    *(__half2*)(C + m * ldc + jc) = hv;
                }
            }
        }
    }
}

// ---------------- launch ----------------------------------------------------
extern "C" void kernel_launch(void* const* d_in, const int* in_sizes, int n_in,
                              void* d_out, int out_size) {
    (void)in_sizes; (void)n_in; (void)out_size;
    const float* x     = (const float*)d_in[0];
    const unsigned char* mask = (const unsigned char*)d_in[1];
    const float* ln1_w = (const float*)d_in[2];
    const float* ln1_b = (const float*)d_in[3];
    const float* ln2_w = (const float*)d_in[4];
    const float* ln2_b = (const float*)d_in[5];
    const float* Wq = (const float*)d_in[6];
    const float* bq = (const float*)d_in[7];
    const float* Wk = (const float*)d_in[8];
    const float* bk = (const float*)d_in[9];
    const float* Wv = (const float*)d_in[10];
    const float* bv = (const float*)d_in[11];
    const float* W1 = (const float*)d_in[12];
    const float* b1 = (const float*)d_in[13];
    const float* W2 = (const float*)d_in[14];
    const float* b2 = (const float*)d_in[15];
    float* out = (float*)d_out;

    __half *lnh, *qkvh, *atth, *h1h, *wh;
    float *x1, *nb, *b3;
    cudaGetSymbolAddress((void**)&lnh,  g_ln);
    cudaGetSymbolAddress((void**)&qkvh, g_qkv);
    cudaGetSymbolAddress((void**)&atth, g_att);
    cudaGetSymbolAddress((void**)&h1h,  g_h1);
    cudaGetSymbolAddress((void**)&x1,   g_x1);
    cudaGetSymbolAddress((void**)&nb,   g_negbias);
    cudaGetSymbolAddress((void**)&wh,   g_wh);
    cudaGetSymbolAddress((void**)&b3,   g_bias3);

    cudaFuncSetAttribute(mma_gemm<2>, cudaFuncAttributeMaxDynamicSharedMemorySize, DSMEM_BYTES);
    cudaFuncSetAttribute(mma_gemm<3>, cudaFuncAttributeMaxDynamicSharedMemorySize, DSMEM_BYTES);
    cudaFuncSetAttribute(mma_gemm<4>, cudaFuncAttributeMaxDynamicSharedMemorySize, DSMEM_BYTES);
    cudaFuncSetAttribute(mma_gemm<5>, cudaFuncAttributeMaxDynamicSharedMemorySize, DSMEM_BYTES);
    cudaFuncSetAttribute(mma_gemm<7>, cudaFuncAttributeMaxDynamicSharedMemorySize, DSMEM_BYTES);

    __half* Qh = qkvh;
    __half* Kh = qkvh + ROWE;
    __half* Vth = qkvh + 2 * ROWE;
    __half* W1h = wh + 3 * EE;
    __half* W2h = wh + 5 * EE;

    const long long SE = (long long)SEQ * EMB;
    const long long SS = (long long)SEQ * SEQ;

    // 1) weights -> fp16 + pack biases
    round_all<<<4096, 256>>>((const float4*)Wq, (const float4*)Wk, (const float4*)Wv,
                             (const float4*)W1, (const float4*)W2, bq, bk, bv);
    // 2) mask -> additive bias
    mask_kernel<<<1, 256>>>(mask);
    // 3) LN1 -> fp16
    ln_kernel<<<ROWS, 256>>>(x, ln1_w, ln1_b, lnh);
    // 4) Q,K,V batched over z (z==2 stores V transposed into Vt)
    mma_gemm<7><<<dim3(EMB / 128, ROWS / 128, 3), 128, DSMEM_BYTES>>>(
        lnh, wh, (void*)qkvh, EMB, EMB, EMB, EMB, b3, x, 1.f,
        0, EE, ROWE, EMB, 0);
    // 5) scores = Q K^T / 32 + maskbias  -> fp16 (in g_att)
    mma_gemm<2><<<dim3(SEQ / 128, SEQ / 128, NB), 128, DSMEM_BYTES>>>(
        Qh, Kh, (void*)atth, EMB, EMB, EMB, SEQ, nb, x, 0.03125f, SE, SE, SS, SEQ, 0);
    // 6) softmax rows, fp16 in place
    softmax_kernel<<<ROWS, 256>>>(atth);
    // 7) x1 = x + attn @ V
    mma_gemm<3><<<dim3(EMB / 128, SEQ / 128, NB), 128, DSMEM_BYTES>>>(
        atth, Vth, (void*)x1, SEQ, SEQ, SEQ, EMB, nb, x, 1.f, SS, SE, SE, 0, SE);
    // 8) LN2 -> fp16
    ln_kernel<<<ROWS, 256>>>(x1, ln2_w, ln2_b, lnh);
    // 9) h1 = relu(h @ W1^T + b1) -> fp16
    mma_gemm<4><<<dim3(2 * EMB / 128, ROWS / 128, 1), 128, DSMEM_BYTES>>>(
        lnh, W1h, (void*)h1h, EMB, EMB, EMB, 2 * EMB, b1, x, 1.f, 0, 0, 0, 0, 0);
    // 10) out = x1 + h1 @ W2^T + b2  (f32 out)
    mma_gemm<5><<<dim3(EMB / 128, ROWS / 128, 1), 128, DSMEM_BYTES>>>(
        h1h, W2h, (void*)out, 2 * EMB, 2 * EMB, 2 * EMB, EMB, b2, x1, 1.f, 0, 0, 0, 0, 0);
}